// round 1
// baseline (speedup 1.0000x reference)
#include <cuda_runtime.h>

// SingleDisCoLoss: BCE + 0.1 * weighted distance-correlation^2 over labels==0 subset.
// N = 8192. Output: 3 floats (total, bce, lambda*dcorr).

#define MAXN 8192
#define TB 256
#define JSPLIT 16
#define DISCO_LAMBDA 0.1

// Scratch (device globals — no allocation allowed)
__device__ float  g_wm[MAXN];   // weights * (label==0)
__device__ float  g_u[MAXN];    // row sums -> a_row (in place)
__device__ float  g_v[MAXN];    // row sums -> b_row (in place)
__device__ double g_bce_sum;
__device__ double g_nf;
__device__ double g_at, g_bt;   // a_tot, b_tot
__device__ double g_sAB, g_sAA, g_sBB;

// ---------------------------------------------------------------------------
// Kernel A: O(N) init — wm array, zero accumulators, BCE sum, nf count.
// Single block.
// ---------------------------------------------------------------------------
__global__ void k_init(const float* __restrict__ p, const int* __restrict__ lab,
                       const float* __restrict__ w, int n) {
    int tid = threadIdx.x;
    double bce = 0.0, nf = 0.0;
    for (int i = tid; i < n; i += TB) {
        int   y  = lab[i];
        float wi = w[i];
        g_wm[i] = (y == 0) ? wi : 0.0f;
        g_u[i]  = 0.0f;
        g_v[i]  = 0.0f;
        float pi     = p[i];
        float logp   = fmaxf(logf(pi),     -100.0f);   // torch-style clamp
        float log1mp = fmaxf(log1pf(-pi),  -100.0f);
        float loss   = (y != 0) ? -logp : -log1mp;     // y in {0,1}
        bce += (double)(wi * loss);
        nf  += (y == 0) ? 1.0 : 0.0;
    }
    __shared__ double sb[TB], sn[TB];
    sb[tid] = bce; sn[tid] = nf;
    __syncthreads();
    for (int s = TB / 2; s > 0; s >>= 1) {
        if (tid < s) { sb[tid] += sb[tid + s]; sn[tid] += sn[tid + s]; }
        __syncthreads();
    }
    if (tid == 0) {
        g_bce_sum = sb[0];
        g_nf      = sn[0];
        g_sAB = 0.0; g_sAA = 0.0; g_sBB = 0.0;
    }
}

// ---------------------------------------------------------------------------
// Kernel B: weighted row sums  u_i = sum_j |p_i - p_j| * wm_j  (and v for t).
// One thread per row i; blockIdx.y splits the j range; broadcast reads from
// shared (all lanes read same k -> conflict-free).
// ---------------------------------------------------------------------------
__global__ void k_rows(const float* __restrict__ p, const float* __restrict__ t, int n) {
    int tid = threadIdx.x;
    int i   = blockIdx.x * TB + tid;
    int jchunk = n / JSPLIT;
    int j0  = blockIdx.y * jchunk;

    float pi = (i < n) ? p[i] : 0.0f;
    float ti = (i < n) ? t[i] : 0.0f;

    __shared__ float sp[TB], st[TB], sw[TB];
    float u = 0.0f, v = 0.0f;

    for (int jt = 0; jt < jchunk; jt += TB) {
        int j = j0 + jt + tid;
        sp[tid] = p[j];
        st[tid] = t[j];
        sw[tid] = g_wm[j];
        __syncthreads();
        #pragma unroll 8
        for (int k = 0; k < TB; k++) {
            float wj = sw[k];
            u = fmaf(fabsf(pi - sp[k]), wj, u);
            v = fmaf(fabsf(ti - st[k]), wj, v);
        }
        __syncthreads();
    }
    if (i < n) {
        atomicAdd(&g_u[i], u);
        atomicAdd(&g_v[i], v);
    }
}

// ---------------------------------------------------------------------------
// Kernel C: scale row sums -> a_row, b_row; reduce a_tot, b_tot. Single block.
// a_row = u/nf ; a_tot = sum(wm * a_row)/nf
// ---------------------------------------------------------------------------
__global__ void k_center(int n) {
    int tid = threadIdx.x;
    float inv_nf = (float)(1.0 / g_nf);
    double Pa = 0.0, Pb = 0.0;
    for (int i = tid; i < n; i += TB) {
        float ar = g_u[i] * inv_nf;
        float br = g_v[i] * inv_nf;
        g_u[i] = ar;
        g_v[i] = br;
        float wm = g_wm[i];
        Pa += (double)(wm * ar);
        Pb += (double)(wm * br);
    }
    __shared__ double sa[TB], sb[TB];
    sa[tid] = Pa; sb[tid] = Pb;
    __syncthreads();
    for (int s = TB / 2; s > 0; s >>= 1) {
        if (tid < s) { sa[tid] += sa[tid + s]; sb[tid] += sb[tid + s]; }
        __syncthreads();
    }
    if (tid == 0) {
        g_at = sa[0] / g_nf;
        g_bt = sb[0] / g_nf;
    }
}

// ---------------------------------------------------------------------------
// Kernel D: pair pass — accumulate
//   S_AB = sum_ij wm_i wm_j A_ij B_ij,  S_AA, S_BB
// with A_ij = |p_i-p_j| - ar_j + (at - ar_i).
// fp32 per-tile partials flushed to per-thread doubles every TB j's.
// ---------------------------------------------------------------------------
__global__ void k_pairs(const float* __restrict__ p, const float* __restrict__ t, int n) {
    int tid = threadIdx.x;
    int i   = blockIdx.x * TB + tid;
    int jchunk = n / JSPLIT;
    int j0  = blockIdx.y * jchunk;

    float at = (float)g_at, bt = (float)g_bt;

    float pi = 0.f, ti = 0.f, wmi = 0.f, ci = 0.f, di = 0.f;
    if (i < n) {
        pi  = p[i];
        ti  = t[i];
        wmi = g_wm[i];
        ci  = at - g_u[i];   // (at - ar_i)
        di  = bt - g_v[i];
    }

    __shared__ float sp[TB], st[TB], sw[TB], sa[TB], sb[TB];
    double dAB = 0.0, dAA = 0.0, dBB = 0.0;

    for (int jt = 0; jt < jchunk; jt += TB) {
        int j = j0 + jt + tid;
        sp[tid] = p[j];
        st[tid] = t[j];
        sw[tid] = g_wm[j];
        sa[tid] = g_u[j];
        sb[tid] = g_v[j];
        __syncthreads();

        float fAB = 0.0f, fAA = 0.0f, fBB = 0.0f;
        #pragma unroll 8
        for (int k = 0; k < TB; k++) {
            float A  = fabsf(pi - sp[k]) + (ci - sa[k]);
            float B  = fabsf(ti - st[k]) + (di - sb[k]);
            float w2 = wmi * sw[k];
            fAB = fmaf(w2, A * B, fAB);
            fAA = fmaf(w2, A * A, fAA);
            fBB = fmaf(w2, B * B, fBB);
        }
        dAB += (double)fAB;
        dAA += (double)fAA;
        dBB += (double)fBB;
        __syncthreads();
    }

    // Block-level double reduction, then one atomicAdd per sum per block.
    __shared__ double red[TB];
    red[tid] = dAB; __syncthreads();
    for (int s = TB / 2; s > 0; s >>= 1) { if (tid < s) red[tid] += red[tid + s]; __syncthreads(); }
    if (tid == 0) atomicAdd(&g_sAB, red[0]);
    __syncthreads();

    red[tid] = dAA; __syncthreads();
    for (int s = TB / 2; s > 0; s >>= 1) { if (tid < s) red[tid] += red[tid + s]; __syncthreads(); }
    if (tid == 0) atomicAdd(&g_sAA, red[0]);
    __syncthreads();

    red[tid] = dBB; __syncthreads();
    for (int s = TB / 2; s > 0; s >>= 1) { if (tid < s) red[tid] += red[tid + s]; __syncthreads(); }
    if (tid == 0) atomicAdd(&g_sBB, red[0]);
}

// ---------------------------------------------------------------------------
// Kernel E: finalize. dcorr (power 2) = (S_AB/nf^2)^2 / ((S_AA/nf^2)(S_BB/nf^2))
//                                     = S_AB^2 / (S_AA * S_BB)   (nf cancels)
// ---------------------------------------------------------------------------
__global__ void k_final(float* __restrict__ out, int n) {
    double bce   = g_bce_sum / (double)n;
    double dcorr = (g_sAB * g_sAB) / (g_sAA * g_sBB);
    double ld    = DISCO_LAMBDA * dcorr;
    out[0] = (float)(bce + ld);
    out[1] = (float)bce;
    out[2] = (float)ld;
}

// ---------------------------------------------------------------------------
extern "C" void kernel_launch(void* const* d_in, const int* in_sizes, int n_in,
                              void* d_out, int out_size) {
    const float* p   = (const float*)d_in[0];  // inferences
    const int*   lab = (const int*)  d_in[1];  // labels
    const float* t   = (const float*)d_in[2];  // disco_target
    const float* w   = (const float*)d_in[3];  // weights
    float* out = (float*)d_out;
    int n = in_sizes[0];

    k_init<<<1, TB>>>(p, lab, w, n);

    dim3 grid((n + TB - 1) / TB, JSPLIT);
    k_rows<<<grid, TB>>>(p, t, n);
    k_center<<<1, TB>>>(n);
    k_pairs<<<grid, TB>>>(p, t, n);
    k_final<<<1, 1>>>(out, n);
}

// round 2
// speedup vs baseline: 1.1930x; 1.1930x over previous
#include <cuda_runtime.h>

// SingleDisCoLoss: BCE + 0.1 * weighted distance-correlation^2 over labels==0 subset.
// N = 8192. Output: 3 floats (total, bce, lambda*dcorr).
// Round 2: f32x2 packed math (2 rows/thread), LDS.128 j-operand packing,
//          parallel init, wmi hoisted to the double flush.

#define MAXN 8192
#define TB 256
#define GY 32              // j-range splits (jchunk = 8192/32 = 256 = one tile)
#define NIB 32             // init blocks
#define DISCO_LAMBDA 0.1
#define ABSMASK 0x7FFFFFFF7FFFFFFFULL

typedef unsigned long long ull;

// Scratch (device globals — no allocation allowed)
__device__ float  g_wm[MAXN];
__device__ float  g_u[MAXN];    // row sums -> a_row (in place)
__device__ float  g_v[MAXN];
__device__ double g_bcep[NIB], g_nfp[NIB];
__device__ double g_bce_sum, g_nf;
__device__ double g_at, g_bt;
__device__ double g_sAB, g_sAA, g_sBB;

// ---- f32x2 helpers --------------------------------------------------------
__device__ __forceinline__ ull pack2(float a, float b) {
    ull r; asm("mov.b64 %0, {%1, %2};" : "=l"(r) : "f"(a), "f"(b)); return r;
}
__device__ __forceinline__ float lo2(ull x) { return __uint_as_float((unsigned)x); }
__device__ __forceinline__ float hi2(ull x) { return __uint_as_float((unsigned)(x >> 32)); }

#define ADD2(out, a, b) asm("add.rn.f32x2 %0, %1, %2;" : "=l"(out) : "l"(a), "l"(b))
#define MUL2(out, a, b) asm("mul.rn.f32x2 %0, %1, %2;" : "=l"(out) : "l"(a), "l"(b))
#define FMA2(acc, a, b) asm("fma.rn.f32x2 %0, %1, %2, %0;" : "+l"(acc) : "l"(a), "l"(b))

// ---- block reduce (3 doubles) --------------------------------------------
__device__ __forceinline__ void warp_red(double& x) {
    #pragma unroll
    for (int o = 16; o > 0; o >>= 1) x += __shfl_down_sync(0xFFFFFFFFu, x, o);
}

// ---------------------------------------------------------------------------
// Kernel A: parallel init — wm array, zero u/v, per-block BCE/nf partials.
// grid = NIB blocks x TB threads = 8192 threads, one element each.
// ---------------------------------------------------------------------------
__global__ void k_init(const float* __restrict__ p, const int* __restrict__ lab,
                       const float* __restrict__ w, int n) {
    int tid = threadIdx.x;
    int idx = blockIdx.x * TB + tid;
    double bce = 0.0, nf = 0.0;
    if (idx < n) {
        int   y  = lab[idx];
        float wi = w[idx];
        g_wm[idx] = (y == 0) ? wi : 0.0f;
        g_u[idx]  = 0.0f;
        g_v[idx]  = 0.0f;
        float pi     = p[idx];
        float logp   = fmaxf(logf(pi),    -100.0f);
        float log1mp = fmaxf(log1pf(-pi), -100.0f);
        float loss   = (y != 0) ? -logp : -log1mp;
        bce = (double)(wi * loss);
        nf  = (y == 0) ? 1.0 : 0.0;
    }
    __shared__ double sb[TB], sn[TB];
    sb[tid] = bce; sn[tid] = nf;
    __syncthreads();
    for (int s = TB / 2; s > 0; s >>= 1) {
        if (tid < s) { sb[tid] += sb[tid + s]; sn[tid] += sn[tid + s]; }
        __syncthreads();
    }
    if (tid == 0) {
        g_bcep[blockIdx.x] = sb[0];
        g_nfp[blockIdx.x]  = sn[0];
        if (blockIdx.x == 0) { g_sAB = 0.0; g_sAA = 0.0; g_sBB = 0.0; }
    }
}

// ---------------------------------------------------------------------------
// Kernel B: weighted row sums, f32x2 (2 rows per thread).
// u_i = sum_j |p_i - p_j| * wm_j ; v_i likewise for t.
// ---------------------------------------------------------------------------
__global__ void k_rows(const float* __restrict__ p, const float* __restrict__ t, int n) {
    int tid = threadIdx.x;
    int i0  = (blockIdx.x * TB + tid) * 2;
    int j0  = blockIdx.y * (n / GY);

    float2 pv = *(const float2*)(p + i0);
    float2 tv = *(const float2*)(t + i0);
    ull pi2 = pack2(pv.x, pv.y);
    ull ti2 = pack2(tv.x, tv.y);

    __shared__ ulonglong2 sPT[TB];   // {-pj dup, -tj dup}
    __shared__ ull        sW[TB];    // {wj dup}

    int j = j0 + tid;
    {
        float pj = p[j], tj = t[j], wj = g_wm[j];
        sPT[tid] = make_ulonglong2(pack2(-pj, -pj), pack2(-tj, -tj));
        sW[tid]  = pack2(wj, wj);
    }
    __syncthreads();

    ull u2 = 0ULL, v2 = 0ULL;
    #pragma unroll 8
    for (int k = 0; k < TB; k++) {
        ulonglong2 pt = sPT[k];
        ull wk = sW[k];
        ull d;
        ADD2(d, pi2, pt.x); d &= ABSMASK; FMA2(u2, d, wk);
        ADD2(d, ti2, pt.y); d &= ABSMASK; FMA2(v2, d, wk);
    }

    atomicAdd(&g_u[i0],     lo2(u2));
    atomicAdd(&g_u[i0 + 1], hi2(u2));
    atomicAdd(&g_v[i0],     lo2(v2));
    atomicAdd(&g_v[i0 + 1], hi2(v2));
}

// ---------------------------------------------------------------------------
// Kernel C: reduce init partials, scale row sums -> a_row/b_row, a_tot/b_tot.
// Single block.
// ---------------------------------------------------------------------------
__global__ void k_center(int n) {
    int tid = threadIdx.x;
    __shared__ double s_nf;
    if (tid < 32) {
        double nf  = g_nfp[tid];
        double bce = g_bcep[tid];
        warp_red(nf);
        warp_red(bce);
        if (tid == 0) { s_nf = nf; g_nf = nf; g_bce_sum = bce; }
    }
    __syncthreads();
    float inv_nf = (float)(1.0 / s_nf);

    double Pa = 0.0, Pb = 0.0;
    for (int i = tid; i < n; i += TB) {
        float ar = g_u[i] * inv_nf;
        float br = g_v[i] * inv_nf;
        g_u[i] = ar;
        g_v[i] = br;
        float wm = g_wm[i];
        Pa += (double)(wm * ar);
        Pb += (double)(wm * br);
    }
    __shared__ double sa[TB], sb[TB];
    sa[tid] = Pa; sb[tid] = Pb;
    __syncthreads();
    for (int s = TB / 2; s > 0; s >>= 1) {
        if (tid < s) { sa[tid] += sa[tid + s]; sb[tid] += sb[tid + s]; }
        __syncthreads();
    }
    if (tid == 0) {
        g_at = sa[0] / s_nf;
        g_bt = sb[0] / s_nf;
    }
}

// ---------------------------------------------------------------------------
// Kernel D: pair pass, f32x2 packed (2 rows per thread).
//   A_ij = |p_i - p_j| + (at - ar_i) - ar_j
//   accumulate S_AB, S_AA, S_BB = sum_ij wm_i wm_j {AB, A^2, B^2}
// wm_i applied at the double flush (constant per row).
// ---------------------------------------------------------------------------
__global__ void k_pairs(const float* __restrict__ p, const float* __restrict__ t, int n) {
    int tid = threadIdx.x;
    int i0  = (blockIdx.x * TB + tid) * 2;
    int j0  = blockIdx.y * (n / GY);

    float at = (float)g_at, bt = (float)g_bt;

    float2 pv = *(const float2*)(p + i0);
    float2 tv = *(const float2*)(t + i0);
    ull pi2 = pack2(pv.x, pv.y);
    ull ti2 = pack2(tv.x, tv.y);
    ull ci2 = pack2(at - g_u[i0], at - g_u[i0 + 1]);
    ull di2 = pack2(bt - g_v[i0], bt - g_v[i0 + 1]);
    float wm0 = g_wm[i0], wm1 = g_wm[i0 + 1];

    __shared__ ulonglong2 sPA[TB];   // {-pj dup, -aj dup}
    __shared__ ulonglong2 sTBv[TB];  // {-tj dup, -bj dup}
    __shared__ ull        sW[TB];    // {wj dup}

    int j = j0 + tid;
    {
        float pj = p[j], tj = t[j], wj = g_wm[j];
        float aj = g_u[j], bj = g_v[j];
        sPA[tid]  = make_ulonglong2(pack2(-pj, -pj), pack2(-aj, -aj));
        sTBv[tid] = make_ulonglong2(pack2(-tj, -tj), pack2(-bj, -bj));
        sW[tid]   = pack2(wj, wj);
    }
    __syncthreads();

    ull fAB = 0ULL, fAA = 0ULL, fBB = 0ULL;
    #pragma unroll 8
    for (int k = 0; k < TB; k++) {
        ulonglong2 pa = sPA[k];
        ulonglong2 tb = sTBv[k];
        ull wk = sW[k];
        ull d, e, A, B, t2, u2;
        ADD2(d, pi2, pa.x); d &= ABSMASK;   // |p_i - p_j|
        ADD2(e, ci2, pa.y);                 // (at - ar_i) - ar_j
        ADD2(A, d, e);
        ADD2(d, ti2, tb.x); d &= ABSMASK;
        ADD2(e, di2, tb.y);
        ADD2(B, d, e);
        MUL2(t2, A, wk);
        MUL2(u2, B, wk);
        FMA2(fAB, t2, B);
        FMA2(fAA, t2, A);
        FMA2(fBB, u2, B);
    }

    // Apply wm_i per half, convert to double.
    double dAB = (double)wm0 * (double)lo2(fAB) + (double)wm1 * (double)hi2(fAB);
    double dAA = (double)wm0 * (double)lo2(fAA) + (double)wm1 * (double)hi2(fAA);
    double dBB = (double)wm0 * (double)lo2(fBB) + (double)wm1 * (double)hi2(fBB);

    // Block reduction: warp shuffles + shared across warps.
    __shared__ double red[3][8];
    int lane = tid & 31, wid = tid >> 5;
    warp_red(dAB); warp_red(dAA); warp_red(dBB);
    if (lane == 0) { red[0][wid] = dAB; red[1][wid] = dAA; red[2][wid] = dBB; }
    __syncthreads();
    if (wid == 0) {
        double a = (lane < 8) ? red[0][lane] : 0.0;
        double b = (lane < 8) ? red[1][lane] : 0.0;
        double c = (lane < 8) ? red[2][lane] : 0.0;
        warp_red(a); warp_red(b); warp_red(c);
        if (lane == 0) {
            atomicAdd(&g_sAB, a);
            atomicAdd(&g_sAA, b);
            atomicAdd(&g_sBB, c);
        }
    }
}

// ---------------------------------------------------------------------------
// Kernel E: finalize. dcorr^2 = S_AB^2 / (S_AA * S_BB)  (nf^2 factors cancel)
// ---------------------------------------------------------------------------
__global__ void k_final(float* __restrict__ out, int n) {
    double bce   = g_bce_sum / (double)n;
    double dcorr = (g_sAB * g_sAB) / (g_sAA * g_sBB);
    double ld    = DISCO_LAMBDA * dcorr;
    out[0] = (float)(bce + ld);
    out[1] = (float)bce;
    out[2] = (float)ld;
}

// ---------------------------------------------------------------------------
extern "C" void kernel_launch(void* const* d_in, const int* in_sizes, int n_in,
                              void* d_out, int out_size) {
    const float* p   = (const float*)d_in[0];  // inferences
    const int*   lab = (const int*)  d_in[1];  // labels
    const float* t   = (const float*)d_in[2];  // disco_target
    const float* w   = (const float*)d_in[3];  // weights
    float* out = (float*)d_out;
    int n = in_sizes[0];

    k_init<<<NIB, TB>>>(p, lab, w, n);

    dim3 grid(n / (TB * 2), GY);   // 16 x 32 = 512 blocks
    k_rows<<<grid, TB>>>(p, t, n);
    k_center<<<1, TB>>>(n);
    k_pairs<<<grid, TB>>>(p, t, n);
    k_final<<<1, 1>>>(out, n);
}

// round 3
// speedup vs baseline: 1.5776x; 1.3223x over previous
#include <cuda_runtime.h>

// SingleDisCoLoss: BCE + 0.1 * weighted distance-correlation^2 over labels==0 subset.
// Round 3: single fused N^2 pass via algebraic expansion of double-centering:
//   S_XY = P_xy + (2W - 4nf) Q_xy + xt*yt*(4nf^2 - 4W nf + W^2)
// where P_xy = sum wm_i wm_j a_ij b_ij is the only O(N^2) term and is computed
// together with the row sums u_i = sum_j wm_j a_ij in ONE pass.
// f32x2 packed math, 4 rows/thread, f32 tile partials -> double.

#define MAXN 8192
#define TB 128               // threads per block (fused kernel)
#define ROWS 4               // i-rows per thread
#define GY 64                // j-range splits; jchunk = 8192/64 = 128 = TB
#define NIB 32               // init blocks (32 x 256 = 8192 threads)
#define ITB 256
#define DISCO_LAMBDA 0.1
#define ABSMASK 0x7FFFFFFF7FFFFFFFULL

typedef unsigned long long ull;

// Scratch (device globals — no allocation allowed)
__device__ float  g_wm[MAXN];
__device__ float  g_u[MAXN];     // raw row sums sum_j wm_j |p_i-p_j|
__device__ float  g_v[MAXN];
__device__ double g_bcep[NIB], g_nfp[NIB], g_Wp[NIB];
__device__ double g_Pab, g_Paa, g_Pbb;

// ---- f32x2 helpers --------------------------------------------------------
__device__ __forceinline__ ull pack2(float a, float b) {
    ull r; asm("mov.b64 %0, {%1, %2};" : "=l"(r) : "f"(a), "f"(b)); return r;
}
__device__ __forceinline__ float lo2(ull x) { return __uint_as_float((unsigned)x); }
__device__ __forceinline__ float hi2(ull x) { return __uint_as_float((unsigned)(x >> 32)); }

#define ADD2(out, a, b) asm("add.rn.f32x2 %0, %1, %2;" : "=l"(out) : "l"(a), "l"(b))
#define MUL2(out, a, b) asm("mul.rn.f32x2 %0, %1, %2;" : "=l"(out) : "l"(a), "l"(b))
#define FMA2(acc, a, b) asm("fma.rn.f32x2 %0, %1, %2, %0;" : "+l"(acc) : "l"(a), "l"(b))

__device__ __forceinline__ void warp_red(double& x) {
    #pragma unroll
    for (int o = 16; o > 0; o >>= 1) x += __shfl_down_sync(0xFFFFFFFFu, x, o);
}

// ---------------------------------------------------------------------------
// Kernel A: parallel init — wm, zero u/v, per-block BCE / nf / W partials.
// ---------------------------------------------------------------------------
__global__ void k_init(const float* __restrict__ p, const int* __restrict__ lab,
                       const float* __restrict__ w, int n) {
    int tid = threadIdx.x;
    int idx = blockIdx.x * ITB + tid;
    double bce = 0.0, nf = 0.0, Wd = 0.0;
    if (idx < n) {
        int   y  = lab[idx];
        float wi = w[idx];
        float wm = (y == 0) ? wi : 0.0f;
        g_wm[idx] = wm;
        g_u[idx]  = 0.0f;
        g_v[idx]  = 0.0f;
        float pi     = p[idx];
        float logp   = fmaxf(logf(pi),    -100.0f);
        float log1mp = fmaxf(log1pf(-pi), -100.0f);
        float loss   = (y != 0) ? -logp : -log1mp;
        bce = (double)(wi * loss);
        nf  = (y == 0) ? 1.0 : 0.0;
        Wd  = (double)wm;
    }
    __shared__ double sb[ITB], sn[ITB], sw[ITB];
    sb[tid] = bce; sn[tid] = nf; sw[tid] = Wd;
    __syncthreads();
    for (int s = ITB / 2; s > 0; s >>= 1) {
        if (tid < s) { sb[tid] += sb[tid + s]; sn[tid] += sn[tid + s]; sw[tid] += sw[tid + s]; }
        __syncthreads();
    }
    if (tid == 0) {
        g_bcep[blockIdx.x] = sb[0];
        g_nfp[blockIdx.x]  = sn[0];
        g_Wp[blockIdx.x]   = sw[0];
        if (blockIdx.x == 0) { g_Pab = 0.0; g_Paa = 0.0; g_Pbb = 0.0; }
    }
}

// ---------------------------------------------------------------------------
// Kernel B: fused N^2 pass. 4 rows/thread (2 packed f32x2 regs per quantity).
//   u_i  += sum_j wm_j |p_i-p_j|       v_i likewise
//   P_ab += wm_i wm_j |dp||dt|,  P_aa += wm_i wm_j dp^2,  P_bb += ... dt^2
// wm_i applied at the flush (per-row constant).
// ---------------------------------------------------------------------------
__global__ void k_fused(const float* __restrict__ p, const float* __restrict__ t, int n) {
    int tid = threadIdx.x;
    int i0  = blockIdx.x * (TB * ROWS) + tid * ROWS;
    int j0  = blockIdx.y * TB;           // jchunk == TB

    float4 pv = *(const float4*)(p + i0);
    float4 tv = *(const float4*)(t + i0);
    ull pA0 = pack2(pv.x, pv.y), pA1 = pack2(pv.z, pv.w);
    ull tA0 = pack2(tv.x, tv.y), tA1 = pack2(tv.z, tv.w);

    __shared__ ulonglong2 sPT[TB];   // {-pj dup, -tj dup}
    __shared__ ull        sW[TB];    // {wm_j dup}
    {
        int j = j0 + tid;
        float pj = p[j], tj = t[j], wj = g_wm[j];
        sPT[tid] = make_ulonglong2(pack2(-pj, -pj), pack2(-tj, -tj));
        sW[tid]  = pack2(wj, wj);
    }
    __syncthreads();

    ull u0 = 0, u1 = 0, v0 = 0, v1 = 0;
    ull ab0 = 0, ab1 = 0, aa0 = 0, aa1 = 0, bb0 = 0, bb1 = 0;

    #pragma unroll 8
    for (int k = 0; k < TB; k++) {
        ulonglong2 pt = sPT[k];
        ull wk = sW[k];
        ull dA, dB, m, m2;
        // rows 0,1
        ADD2(dA, pA0, pt.x); dA &= ABSMASK;
        ADD2(dB, tA0, pt.y); dB &= ABSMASK;
        FMA2(u0, dA, wk);
        FMA2(v0, dB, wk);
        MUL2(m, dA, wk);
        FMA2(ab0, m, dB);
        FMA2(aa0, m, dA);
        MUL2(m2, dB, wk);
        FMA2(bb0, m2, dB);
        // rows 2,3
        ADD2(dA, pA1, pt.x); dA &= ABSMASK;
        ADD2(dB, tA1, pt.y); dB &= ABSMASK;
        FMA2(u1, dA, wk);
        FMA2(v1, dB, wk);
        MUL2(m, dA, wk);
        FMA2(ab1, m, dB);
        FMA2(aa1, m, dA);
        MUL2(m2, dB, wk);
        FMA2(bb1, m2, dB);
    }

    // Row sums: atomic f32 accumulation across j-chunks.
    atomicAdd(&g_u[i0 + 0], lo2(u0));
    atomicAdd(&g_u[i0 + 1], hi2(u0));
    atomicAdd(&g_u[i0 + 2], lo2(u1));
    atomicAdd(&g_u[i0 + 3], hi2(u1));
    atomicAdd(&g_v[i0 + 0], lo2(v0));
    atomicAdd(&g_v[i0 + 1], hi2(v0));
    atomicAdd(&g_v[i0 + 2], lo2(v1));
    atomicAdd(&g_v[i0 + 3], hi2(v1));

    // Apply wm_i per row, accumulate in double.
    double w0 = (double)g_wm[i0 + 0], w1 = (double)g_wm[i0 + 1];
    double w2 = (double)g_wm[i0 + 2], w3 = (double)g_wm[i0 + 3];
    double dAB = w0 * lo2(ab0) + w1 * hi2(ab0) + w2 * lo2(ab1) + w3 * hi2(ab1);
    double dAA = w0 * lo2(aa0) + w1 * hi2(aa0) + w2 * lo2(aa1) + w3 * hi2(aa1);
    double dBB = w0 * lo2(bb0) + w1 * hi2(bb0) + w2 * lo2(bb1) + w3 * hi2(bb1);

    // Block reduction (4 warps) + 3 atomicAdds per block.
    __shared__ double red[3][4];
    int lane = tid & 31, wid = tid >> 5;
    warp_red(dAB); warp_red(dAA); warp_red(dBB);
    if (lane == 0) { red[0][wid] = dAB; red[1][wid] = dAA; red[2][wid] = dBB; }
    __syncthreads();
    if (tid == 0) {
        double a = red[0][0] + red[0][1] + red[0][2] + red[0][3];
        double b = red[1][0] + red[1][1] + red[1][2] + red[1][3];
        double c = red[2][0] + red[2][1] + red[2][2] + red[2][3];
        atomicAdd(&g_Pab, a);
        atomicAdd(&g_Paa, b);
        atomicAdd(&g_Pbb, c);
    }
}

// ---------------------------------------------------------------------------
// Kernel C: finish. Single block. Reduces init partials, computes Q sums,
// combines via the expansion identity, writes the 3 outputs.
// ---------------------------------------------------------------------------
__global__ void k_finish(float* __restrict__ out, int n) {
    int tid = threadIdx.x;
    __shared__ double s_nf, s_W, s_bce;
    if (tid < 32) {
        double nf  = g_nfp[tid];
        double bce = g_bcep[tid];
        double Wd  = g_Wp[tid];
        warp_red(nf); warp_red(bce); warp_red(Wd);
        if (tid == 0) { s_nf = nf; s_bce = bce; s_W = Wd; }
    }
    __syncthreads();

    // Sa = sum wm*u, Sb = sum wm*v, Qab = sum wm*u*v, Qaa = sum wm*u^2, Qbb = sum wm*v^2
    double Sa = 0, Sb = 0, Qab = 0, Qaa = 0, Qbb = 0;
    for (int i = tid; i < n; i += ITB) {
        double wm = (double)g_wm[i];
        double u  = (double)g_u[i];
        double v  = (double)g_v[i];
        Sa  += wm * u;
        Sb  += wm * v;
        Qab += wm * u * v;
        Qaa += wm * u * u;
        Qbb += wm * v * v;
    }
    __shared__ double r[5][8];
    int lane = tid & 31, wid = tid >> 5;
    warp_red(Sa); warp_red(Sb); warp_red(Qab); warp_red(Qaa); warp_red(Qbb);
    if (lane == 0) { r[0][wid] = Sa; r[1][wid] = Sb; r[2][wid] = Qab; r[3][wid] = Qaa; r[4][wid] = Qbb; }
    __syncthreads();

    if (tid == 0) {
        double sa = 0, sb = 0, qab = 0, qaa = 0, qbb = 0;
        #pragma unroll
        for (int k = 0; k < ITB / 32; k++) {
            sa += r[0][k]; sb += r[1][k]; qab += r[2][k]; qaa += r[3][k]; qbb += r[4][k];
        }
        double nf = s_nf, W = s_W;
        double inv2 = 1.0 / (nf * nf);
        double at = sa * inv2;            // a_tot (u raw => /nf^2)
        double bt = sb * inv2;
        double cQ = (2.0 * W - 4.0 * nf) * inv2;            // coeff of raw Q (Q/nf^2)
        double cT = 4.0 * nf * nf - 4.0 * W * nf + W * W;   // coeff of xt*yt

        double SAB = g_Pab + cQ * qab + at * bt * cT;
        double SAA = g_Paa + cQ * qaa + at * at * cT;
        double SBB = g_Pbb + cQ * qbb + bt * bt * cT;

        double bce   = s_bce / (double)n;
        double dcorr = (SAB * SAB) / (SAA * SBB);
        double ld    = DISCO_LAMBDA * dcorr;
        out[0] = (float)(bce + ld);
        out[1] = (float)bce;
        out[2] = (float)ld;
    }
}

// ---------------------------------------------------------------------------
extern "C" void kernel_launch(void* const* d_in, const int* in_sizes, int n_in,
                              void* d_out, int out_size) {
    const float* p   = (const float*)d_in[0];  // inferences
    const int*   lab = (const int*)  d_in[1];  // labels
    const float* t   = (const float*)d_in[2];  // disco_target
    const float* w   = (const float*)d_in[3];  // weights
    float* out = (float*)d_out;
    int n = in_sizes[0];

    k_init<<<(n + ITB - 1) / ITB, ITB>>>(p, lab, w, n);

    dim3 grid(n / (TB * ROWS), GY);   // 16 x 64 = 1024 blocks of 128 threads
    k_fused<<<grid, TB>>>(p, t, n);

    k_finish<<<1, ITB>>>(out, n);
}

// round 4
// speedup vs baseline: 1.6289x; 1.0326x over previous
#include <cuda_runtime.h>

// SingleDisCoLoss: BCE + 0.1 * weighted dcorr^2 over labels==0 subset. N=8192.
// Round 4: N^2 loop reduced to P_ab only.
//   P_aa, P_bb: closed form O(N) (squares need no abs).
//   u_i, v_i:   exact via monotone 256-bucket prefix sums + in-bucket pairs.
//   S_XY = P_xy + (2W-4nf)/nf^2 * Q_xy + xt*yt*(4nf^2-4W nf+W^2)  [verified R3]

#define MAXN 8192
#define NB   256        // buckets
#define CAP  256        // bucket member capacity (way above max occupancy)
#define TB4  128
#define ROWS 4
#define GY   64
#define K1B  32
#define K1T  256
#define DISCO_LAMBDA 0.1
#define ABSMASK 0x7FFFFFFF7FFFFFFFULL

typedef unsigned long long ull;

// ---- scratch (device globals; zero-initialized at load, re-zeroed by k_final)
__device__ float  g_wm[MAXN];
__device__ double g_Wbp[NB], g_Xbp[NB], g_Wbt[NB], g_Xbt[NB];
__device__ int    g_cntp[NB], g_cntt[NB];
__device__ float2 g_mp[NB * CAP], g_mt[NB * CAP];   // {value, wm}
__device__ double g_part[7][K1B];   // bce, nf, W, Sp, Sp2, St, St2 (direct store)
__device__ double g_S[5];           // sa, sb, qab, qaa, qbb (atomic)
__device__ double g_Pab;            // atomic

// ---- helpers --------------------------------------------------------------
__device__ __forceinline__ ull pack2(float a, float b) {
    ull r; asm("mov.b64 %0, {%1, %2};" : "=l"(r) : "f"(a), "f"(b)); return r;
}
__device__ __forceinline__ float lo2(ull x) { return __uint_as_float((unsigned)x); }
__device__ __forceinline__ float hi2(ull x) { return __uint_as_float((unsigned)(x >> 32)); }
#define ADD2(out, a, b) asm("add.rn.f32x2 %0, %1, %2;" : "=l"(out) : "l"(a), "l"(b))
#define MUL2(out, a, b) asm("mul.rn.f32x2 %0, %1, %2;" : "=l"(out) : "l"(a), "l"(b))
#define FMA2(acc, a, b) asm("fma.rn.f32x2 %0, %1, %2, %0;" : "+l"(acc) : "l"(a), "l"(b))

__device__ __forceinline__ void warp_red(double& x) {
    #pragma unroll
    for (int o = 16; o > 0; o >>= 1) x += __shfl_down_sync(0xFFFFFFFFu, x, o);
}
__device__ __forceinline__ int buck_p(float p) {
    int b = (int)(p * 256.0f);
    return min(NB - 1, max(0, b));
}
__device__ __forceinline__ int buck_t(float t) {
    int b = (int)((t + 4.5f) * (256.0f / 9.0f));
    return min(NB - 1, max(0, b));
}

// ---------------------------------------------------------------------------
// K1: per-element prep. wm array, bucket histograms + member lists,
//     per-block partials: bce, nf, W, Sp, Sp2, St, St2.
// ---------------------------------------------------------------------------
__global__ void k_prep(const float* __restrict__ p, const int* __restrict__ lab,
                       const float* __restrict__ t, const float* __restrict__ w, int n) {
    int tid = threadIdx.x;
    int idx = blockIdx.x * K1T + tid;
    double acc[7] = {0, 0, 0, 0, 0, 0, 0};
    if (idx < n) {
        int   y  = lab[idx];
        float wi = w[idx];
        float wm = (y == 0) ? wi : 0.0f;
        g_wm[idx] = wm;
        float pi = p[idx];
        float ti = t[idx];

        int bp = buck_p(pi);
        atomicAdd(&g_Wbp[bp], (double)wm);
        atomicAdd(&g_Xbp[bp], (double)wm * (double)pi);
        int sp_ = atomicAdd(&g_cntp[bp], 1);
        if (sp_ < CAP) g_mp[bp * CAP + sp_] = make_float2(pi, wm);

        int bt = buck_t(ti);
        atomicAdd(&g_Wbt[bt], (double)wm);
        atomicAdd(&g_Xbt[bt], (double)wm * (double)ti);
        int st_ = atomicAdd(&g_cntt[bt], 1);
        if (st_ < CAP) g_mt[bt * CAP + st_] = make_float2(ti, wm);

        float logp   = fmaxf(logf(pi),    -100.0f);
        float log1mp = fmaxf(log1pf(-pi), -100.0f);
        float loss   = (y != 0) ? -logp : -log1mp;
        acc[0] = (double)(wi * loss);          // bce
        acc[1] = (y == 0) ? 1.0 : 0.0;         // nf
        acc[2] = (double)wm;                   // W
        acc[3] = (double)wm * pi;              // Sp
        acc[4] = (double)wm * pi * pi;         // Sp2
        acc[5] = (double)wm * ti;              // St
        acc[6] = (double)wm * ti * ti;         // St2
    }
    __shared__ double red[7][8];
    int lane = tid & 31, wid = tid >> 5;
    #pragma unroll
    for (int q = 0; q < 7; q++) warp_red(acc[q]);
    if (lane == 0) {
        #pragma unroll
        for (int q = 0; q < 7; q++) red[q][wid] = acc[q];
    }
    __syncthreads();
    if (tid == 0) {
        #pragma unroll
        for (int q = 0; q < 7; q++) {
            double s = 0;
            #pragma unroll
            for (int k = 0; k < K1T / 32; k++) s += red[q][k];
            g_part[q][blockIdx.x] = s;
        }
    }
}

// ---------------------------------------------------------------------------
// K2: exact u_i, v_i via bucket prefix sums; accumulate Q sums.
// 32 blocks x 256 threads; each block redundantly scans the 256 buckets.
// ---------------------------------------------------------------------------
__global__ void k_uv(const float* __restrict__ p, const float* __restrict__ t, int n) {
    int tid = threadIdx.x;
    __shared__ double sIWp[NB], sIXp[NB], sRWp[NB], sRXp[NB];
    __shared__ double sIWt[NB], sIXt[NB], sRWt[NB], sRXt[NB];

    // load raw + copy for inclusive scan
    {
        double a = g_Wbp[tid], b = g_Xbp[tid], c = g_Wbt[tid], d = g_Xbt[tid];
        sRWp[tid] = a; sIWp[tid] = a;
        sRXp[tid] = b; sIXp[tid] = b;
        sRWt[tid] = c; sIWt[tid] = c;
        sRXt[tid] = d; sIXt[tid] = d;
    }
    __syncthreads();
    // Hillis-Steele inclusive scan over 256 entries, 4 arrays together
    for (int off = 1; off < NB; off <<= 1) {
        double a = 0, b = 0, c = 0, d = 0;
        if (tid >= off) {
            a = sIWp[tid - off]; b = sIXp[tid - off];
            c = sIWt[tid - off]; d = sIXt[tid - off];
        }
        __syncthreads();
        sIWp[tid] += a; sIXp[tid] += b; sIWt[tid] += c; sIXt[tid] += d;
        __syncthreads();
    }

    int i = blockIdx.x * 256 + tid;
    float pi  = p[i];
    float ti  = t[i];
    float wmi = g_wm[i];

    double Wtp = sIWp[NB - 1], Xtp = sIXp[NB - 1];
    double Wtt = sIWt[NB - 1], Xtt = sIXt[NB - 1];

    // u_i
    double u;
    {
        int b = buck_p(pi);
        double Wlo = sIWp[b] - sRWp[b];
        double Xlo = sIXp[b] - sRXp[b];
        double Whi = Wtp - sIWp[b];
        double Xhi = Xtp - sIXp[b];
        u = (double)pi * (Wlo - Whi) - Xlo + Xhi;
        int c = min(g_cntp[b], CAP);
        float s = 0.0f;
        const float2* m = &g_mp[b * CAP];
        for (int k = 0; k < c; k++) {
            float2 e = m[k];
            s = fmaf(e.y, fabsf(pi - e.x), s);
        }
        u += (double)s;
    }
    // v_i
    double v;
    {
        int b = buck_t(ti);
        double Wlo = sIWt[b] - sRWt[b];
        double Xlo = sIXt[b] - sRXt[b];
        double Whi = Wtt - sIWt[b];
        double Xhi = Xtt - sIXt[b];
        v = (double)ti * (Wlo - Whi) - Xlo + Xhi;
        int c = min(g_cntt[b], CAP);
        float s = 0.0f;
        const float2* m = &g_mt[b * CAP];
        for (int k = 0; k < c; k++) {
            float2 e = m[k];
            s = fmaf(e.y, fabsf(ti - e.x), s);
        }
        v += (double)s;
    }

    double acc[5];
    acc[0] = (double)wmi * u;        // sa
    acc[1] = (double)wmi * v;        // sb
    acc[2] = (double)wmi * u * v;    // qab
    acc[3] = (double)wmi * u * u;    // qaa
    acc[4] = (double)wmi * v * v;    // qbb

    __shared__ double red[5][8];
    int lane = tid & 31, wid = tid >> 5;
    #pragma unroll
    for (int q = 0; q < 5; q++) warp_red(acc[q]);
    if (lane == 0) {
        #pragma unroll
        for (int q = 0; q < 5; q++) red[q][wid] = acc[q];
    }
    __syncthreads();
    if (tid == 0) {
        #pragma unroll
        for (int q = 0; q < 5; q++) {
            double s = 0;
            #pragma unroll
            for (int k = 0; k < 8; k++) s += red[q][k];
            atomicAdd(&g_S[q], s);
        }
    }
}

// ---------------------------------------------------------------------------
// K3: the N^2 pass — ONLY P_ab = sum wm_i wm_j |dp||dt| = sum wm_i wm_j |dp*dt|.
// 4 rows/thread, f32x2 packed; 4 fp2 + 2 LOP3 per 2 pairs.
// ---------------------------------------------------------------------------
__global__ void k_pab(const float* __restrict__ p, const float* __restrict__ t, int n) {
    int tid = threadIdx.x;
    int i0  = blockIdx.x * (TB4 * ROWS) + tid * ROWS;
    int j0  = blockIdx.y * TB4;

    float4 pv = *(const float4*)(p + i0);
    float4 tv = *(const float4*)(t + i0);
    ull pA0 = pack2(pv.x, pv.y), pA1 = pack2(pv.z, pv.w);
    ull tA0 = pack2(tv.x, tv.y), tA1 = pack2(tv.z, tv.w);

    __shared__ ulonglong2 sPT[TB4];  // {-pj dup, -tj dup}
    __shared__ ull        sW[TB4];   // {wm_j dup}
    {
        int j = j0 + tid;
        float pj = p[j], tj = t[j], wj = g_wm[j];
        sPT[tid] = make_ulonglong2(pack2(-pj, -pj), pack2(-tj, -tj));
        sW[tid]  = pack2(wj, wj);
    }
    __syncthreads();

    ull ab0 = 0, ab1 = 0;
    #pragma unroll 8
    for (int k = 0; k < TB4; k++) {
        ulonglong2 pt = sPT[k];
        ull wk = sW[k];
        ull dA, dB, m;
        ADD2(dA, pA0, pt.x);
        ADD2(dB, tA0, pt.y);
        MUL2(m, dA, dB); m &= ABSMASK;   // |dp*dt| == |dp||dt|
        FMA2(ab0, m, wk);
        ADD2(dA, pA1, pt.x);
        ADD2(dB, tA1, pt.y);
        MUL2(m, dA, dB); m &= ABSMASK;
        FMA2(ab1, m, wk);
    }

    double w0 = (double)g_wm[i0 + 0], w1 = (double)g_wm[i0 + 1];
    double w2 = (double)g_wm[i0 + 2], w3 = (double)g_wm[i0 + 3];
    double dAB = w0 * lo2(ab0) + w1 * hi2(ab0) + w2 * lo2(ab1) + w3 * hi2(ab1);

    __shared__ double red[4];
    int lane = tid & 31, wid = tid >> 5;
    warp_red(dAB);
    if (lane == 0) red[wid] = dAB;
    __syncthreads();
    if (tid == 0) atomicAdd(&g_Pab, red[0] + red[1] + red[2] + red[3]);
}

// ---------------------------------------------------------------------------
// K4: finalize + re-zero scratch for the next (graph-replayed) call.
// ---------------------------------------------------------------------------
__global__ void k_final(float* __restrict__ out, int n) {
    int tid = threadIdx.x;
    if (tid == 0) {
        double pr[7];
        #pragma unroll
        for (int q = 0; q < 7; q++) {
            double s = 0;
            for (int k = 0; k < K1B; k++) s += g_part[q][k];
            pr[q] = s;
        }
        double bce_s = pr[0], nf = pr[1], W = pr[2];
        double Sp = pr[3], Sp2 = pr[4], St = pr[5], St2 = pr[6];

        double Paa = 2.0 * (W * Sp2 - Sp * Sp);
        double Pbb = 2.0 * (W * St2 - St * St);
        double sa = g_S[0], sb = g_S[1], qab = g_S[2], qaa = g_S[3], qbb = g_S[4];

        double inv2 = 1.0 / (nf * nf);
        double at = sa * inv2;
        double bt = sb * inv2;
        double cQ = (2.0 * W - 4.0 * nf) * inv2;
        double cT = 4.0 * nf * nf - 4.0 * W * nf + W * W;

        double SAB = g_Pab + cQ * qab + at * bt * cT;
        double SAA = Paa   + cQ * qaa + at * at * cT;
        double SBB = Pbb   + cQ * qbb + bt * bt * cT;

        double bce   = bce_s / (double)n;
        double dcorr = (SAB * SAB) / (SAA * SBB);
        double ld    = DISCO_LAMBDA * dcorr;
        out[0] = (float)(bce + ld);
        out[1] = (float)bce;
        out[2] = (float)ld;
    }
    __syncthreads();
    // re-zero accumulators used by atomics (tid covers 0..255 == NB)
    g_Wbp[tid] = 0.0; g_Xbp[tid] = 0.0;
    g_Wbt[tid] = 0.0; g_Xbt[tid] = 0.0;
    g_cntp[tid] = 0;  g_cntt[tid] = 0;
    if (tid < 5) g_S[tid] = 0.0;
    if (tid == 0) g_Pab = 0.0;
}

// ---------------------------------------------------------------------------
extern "C" void kernel_launch(void* const* d_in, const int* in_sizes, int n_in,
                              void* d_out, int out_size) {
    const float* p   = (const float*)d_in[0];  // inferences
    const int*   lab = (const int*)  d_in[1];  // labels
    const float* t   = (const float*)d_in[2];  // disco_target
    const float* w   = (const float*)d_in[3];  // weights
    float* out = (float*)d_out;
    int n = in_sizes[0];

    k_prep<<<K1B, K1T>>>(p, lab, t, w, n);
    k_uv<<<n / 256, 256>>>(p, t, n);
    dim3 grid(n / (TB4 * ROWS), GY);   // 16 x 64 = 1024 blocks of 128
    k_pab<<<grid, TB4>>>(p, t, n);
    k_final<<<1, 256>>>(out, n);
}

// round 5
// speedup vs baseline: 1.7991x; 1.1045x over previous
#include <cuda_runtime.h>

// SingleDisCoLoss: BCE + 0.1 * weighted dcorr^2 over labels==0 subset. N=8192.
// Round 5: 3 launches. k_final folded into last block of k_pab (ticket).
//   P_aa, P_bb: closed form O(N).
//   u_i, v_i:   exact via monotone 256-bucket prefix sums + in-bucket pairs.
//   S_XY = P_xy + (2W-4nf)/nf^2 * Q_xy + xt*yt*(4nf^2-4W nf+W^2)

#define MAXN 8192
#define NB   256        // buckets
#define CAP  256        // bucket member capacity
#define TB4  128
#define ROWS 4
#define GY   64
#define NBLK ((MAXN / (TB4 * ROWS)) * GY)   // 1024
#define K1B  32
#define K1T  256
#define DISCO_LAMBDA 0.1
#define ABSMASK 0x7FFFFFFF7FFFFFFFULL

typedef unsigned long long ull;

// ---- scratch (device globals; zero at load; re-zeroed by finalize path) ----
__device__ float  g_wm[MAXN];
__device__ double g_Wbp[NB], g_Xbp[NB], g_Wbt[NB], g_Xbt[NB];
__device__ int    g_cntp[NB], g_cntt[NB];
__device__ float2 g_mp[NB * CAP], g_mt[NB * CAP];   // {value, wm}
__device__ double g_part[7][K1B];   // bce, nf, W, Sp, Sp2, St, St2
__device__ double g_S[5];           // sa, sb, qab, qaa, qbb (atomic)
__device__ double g_Pab;            // atomic
__device__ unsigned g_ticket;

// ---- helpers --------------------------------------------------------------
__device__ __forceinline__ ull pack2(float a, float b) {
    ull r; asm("mov.b64 %0, {%1, %2};" : "=l"(r) : "f"(a), "f"(b)); return r;
}
__device__ __forceinline__ float lo2(ull x) { return __uint_as_float((unsigned)x); }
__device__ __forceinline__ float hi2(ull x) { return __uint_as_float((unsigned)(x >> 32)); }
#define ADD2(out, a, b) asm("add.rn.f32x2 %0, %1, %2;" : "=l"(out) : "l"(a), "l"(b))
#define MUL2(out, a, b) asm("mul.rn.f32x2 %0, %1, %2;" : "=l"(out) : "l"(a), "l"(b))
#define FMA2(acc, a, b) asm("fma.rn.f32x2 %0, %1, %2, %0;" : "+l"(acc) : "l"(a), "l"(b))

__device__ __forceinline__ void warp_red(double& x) {
    #pragma unroll
    for (int o = 16; o > 0; o >>= 1) x += __shfl_down_sync(0xFFFFFFFFu, x, o);
}
__device__ __forceinline__ int buck_p(float p) {
    int b = (int)(p * 256.0f);
    return min(NB - 1, max(0, b));
}
__device__ __forceinline__ int buck_t(float t) {
    int b = (int)((t + 4.5f) * (256.0f / 9.0f));
    return min(NB - 1, max(0, b));
}

// ---------------------------------------------------------------------------
// K1: prep. wm, bucket hists (shared-first), member lists, 7 per-block partials.
// ---------------------------------------------------------------------------
__global__ void k_prep(const float* __restrict__ p, const int* __restrict__ lab,
                       const float* __restrict__ t, const float* __restrict__ w, int n) {
    int tid = threadIdx.x;
    int idx = blockIdx.x * K1T + tid;

    __shared__ double hWp[NB], hXp[NB], hWt[NB], hXt[NB];
    hWp[tid] = 0.0; hXp[tid] = 0.0; hWt[tid] = 0.0; hXt[tid] = 0.0;
    __syncthreads();

    double acc[7] = {0, 0, 0, 0, 0, 0, 0};
    {
        int   y  = lab[idx];
        float wi = w[idx];
        float wm = (y == 0) ? wi : 0.0f;
        g_wm[idx] = wm;
        float pi = p[idx];
        float ti = t[idx];

        int bp = buck_p(pi);
        atomicAdd(&hWp[bp], (double)wm);
        atomicAdd(&hXp[bp], (double)wm * (double)pi);
        int sp_ = atomicAdd(&g_cntp[bp], 1);
        if (sp_ < CAP) g_mp[bp * CAP + sp_] = make_float2(pi, wm);

        int bt = buck_t(ti);
        atomicAdd(&hWt[bt], (double)wm);
        atomicAdd(&hXt[bt], (double)wm * (double)ti);
        int st_ = atomicAdd(&g_cntt[bt], 1);
        if (st_ < CAP) g_mt[bt * CAP + st_] = make_float2(ti, wm);

        float logp   = fmaxf(logf(pi),    -100.0f);
        float log1mp = fmaxf(log1pf(-pi), -100.0f);
        float loss   = (y != 0) ? -logp : -log1mp;
        acc[0] = (double)(wi * loss);
        acc[1] = (y == 0) ? 1.0 : 0.0;
        acc[2] = (double)wm;
        acc[3] = (double)wm * pi;
        acc[4] = (double)wm * pi * pi;
        acc[5] = (double)wm * ti;
        acc[6] = (double)wm * ti * ti;
    }
    __syncthreads();
    // flush shared buckets: one global atomic per bucket per block (if nonzero)
    if (hWp[tid] != 0.0) { atomicAdd(&g_Wbp[tid], hWp[tid]); atomicAdd(&g_Xbp[tid], hXp[tid]); }
    if (hWt[tid] != 0.0) { atomicAdd(&g_Wbt[tid], hWt[tid]); atomicAdd(&g_Xbt[tid], hXt[tid]); }

    __shared__ double red[7][8];
    int lane = tid & 31, wid = tid >> 5;
    #pragma unroll
    for (int q = 0; q < 7; q++) warp_red(acc[q]);
    if (lane == 0) {
        #pragma unroll
        for (int q = 0; q < 7; q++) red[q][wid] = acc[q];
    }
    __syncthreads();
    if (tid == 0) {
        #pragma unroll
        for (int q = 0; q < 7; q++) {
            double s = 0;
            #pragma unroll
            for (int k = 0; k < K1T / 32; k++) s += red[q][k];
            g_part[q][blockIdx.x] = s;
        }
    }
}

// ---------------------------------------------------------------------------
// K2: exact u_i, v_i via bucket prefix sums; accumulate Q sums (atomic g_S).
// ---------------------------------------------------------------------------
__global__ void k_uv(const float* __restrict__ p, const float* __restrict__ t, int n) {
    int tid = threadIdx.x;
    __shared__ double sIWp[NB], sIXp[NB], sRWp[NB], sRXp[NB];
    __shared__ double sIWt[NB], sIXt[NB], sRWt[NB], sRXt[NB];
    {
        double a = g_Wbp[tid], b = g_Xbp[tid], c = g_Wbt[tid], d = g_Xbt[tid];
        sRWp[tid] = a; sIWp[tid] = a;
        sRXp[tid] = b; sIXp[tid] = b;
        sRWt[tid] = c; sIWt[tid] = c;
        sRXt[tid] = d; sIXt[tid] = d;
    }
    __syncthreads();
    for (int off = 1; off < NB; off <<= 1) {
        double a = 0, b = 0, c = 0, d = 0;
        if (tid >= off) {
            a = sIWp[tid - off]; b = sIXp[tid - off];
            c = sIWt[tid - off]; d = sIXt[tid - off];
        }
        __syncthreads();
        sIWp[tid] += a; sIXp[tid] += b; sIWt[tid] += c; sIXt[tid] += d;
        __syncthreads();
    }

    int i = blockIdx.x * 256 + tid;
    float pi  = p[i];
    float ti  = t[i];
    float wmi = g_wm[i];

    double Wtp = sIWp[NB - 1], Xtp = sIXp[NB - 1];
    double Wtt = sIWt[NB - 1], Xtt = sIXt[NB - 1];

    double u;
    {
        int b = buck_p(pi);
        double Wlo = sIWp[b] - sRWp[b];
        double Xlo = sIXp[b] - sRXp[b];
        double Whi = Wtp - sIWp[b];
        double Xhi = Xtp - sIXp[b];
        u = (double)pi * (Wlo - Whi) - Xlo + Xhi;
        int c = min(g_cntp[b], CAP);
        float s = 0.0f;
        const float2* m = &g_mp[b * CAP];
        for (int k = 0; k < c; k++) {
            float2 e = m[k];
            s = fmaf(e.y, fabsf(pi - e.x), s);
        }
        u += (double)s;
    }
    double v;
    {
        int b = buck_t(ti);
        double Wlo = sIWt[b] - sRWt[b];
        double Xlo = sIXt[b] - sRXt[b];
        double Whi = Wtt - sIWt[b];
        double Xhi = Xtt - sIXt[b];
        v = (double)ti * (Wlo - Whi) - Xlo + Xhi;
        int c = min(g_cntt[b], CAP);
        float s = 0.0f;
        const float2* m = &g_mt[b * CAP];
        for (int k = 0; k < c; k++) {
            float2 e = m[k];
            s = fmaf(e.y, fabsf(ti - e.x), s);
        }
        v += (double)s;
    }

    double acc[5];
    acc[0] = (double)wmi * u;
    acc[1] = (double)wmi * v;
    acc[2] = (double)wmi * u * v;
    acc[3] = (double)wmi * u * u;
    acc[4] = (double)wmi * v * v;

    __shared__ double red[5][8];
    int lane = tid & 31, wid = tid >> 5;
    #pragma unroll
    for (int q = 0; q < 5; q++) warp_red(acc[q]);
    if (lane == 0) {
        #pragma unroll
        for (int q = 0; q < 5; q++) red[q][wid] = acc[q];
    }
    __syncthreads();
    if (tid == 0) {
        #pragma unroll
        for (int q = 0; q < 5; q++) {
            double s = 0;
            #pragma unroll
            for (int k = 0; k < 8; k++) s += red[q][k];
            atomicAdd(&g_S[q], s);
        }
    }
}

// ---------------------------------------------------------------------------
// K3: N^2 pass (P_ab only) + last-block finalize.
// ---------------------------------------------------------------------------
__global__ void k_pab(const float* __restrict__ p, const float* __restrict__ t,
                      float* __restrict__ out, int n) {
    int tid = threadIdx.x;
    int i0  = blockIdx.x * (TB4 * ROWS) + tid * ROWS;
    int j0  = blockIdx.y * TB4;

    float4 pv = *(const float4*)(p + i0);
    float4 tv = *(const float4*)(t + i0);
    ull pA0 = pack2(pv.x, pv.y), pA1 = pack2(pv.z, pv.w);
    ull tA0 = pack2(tv.x, tv.y), tA1 = pack2(tv.z, tv.w);

    __shared__ ulonglong2 sPT[TB4];  // {-pj dup, -tj dup}
    __shared__ ull        sW[TB4];   // {wm_j dup}
    {
        int j = j0 + tid;
        float pj = p[j], tj = t[j], wj = g_wm[j];
        sPT[tid] = make_ulonglong2(pack2(-pj, -pj), pack2(-tj, -tj));
        sW[tid]  = pack2(wj, wj);
    }
    __syncthreads();

    ull ab0 = 0, ab1 = 0;
    #pragma unroll 8
    for (int k = 0; k < TB4; k++) {
        ulonglong2 pt = sPT[k];
        ull wk = sW[k];
        ull dA, dB, m;
        ADD2(dA, pA0, pt.x);
        ADD2(dB, tA0, pt.y);
        MUL2(m, dA, dB); m &= ABSMASK;   // |dp*dt| == |dp||dt|
        FMA2(ab0, m, wk);
        ADD2(dA, pA1, pt.x);
        ADD2(dB, tA1, pt.y);
        MUL2(m, dA, dB); m &= ABSMASK;
        FMA2(ab1, m, wk);
    }

    double w0 = (double)g_wm[i0 + 0], w1 = (double)g_wm[i0 + 1];
    double w2 = (double)g_wm[i0 + 2], w3 = (double)g_wm[i0 + 3];
    double dAB = w0 * lo2(ab0) + w1 * hi2(ab0) + w2 * lo2(ab1) + w3 * hi2(ab1);

    __shared__ double red[4];
    int lane = tid & 31, wid = tid >> 5;
    warp_red(dAB);
    if (lane == 0) red[wid] = dAB;
    __syncthreads();

    __shared__ bool amLast;
    if (tid == 0) {
        atomicAdd(&g_Pab, red[0] + red[1] + red[2] + red[3]);
        __threadfence();
        unsigned v = atomicAdd(&g_ticket, 1u);
        amLast = (v == (unsigned)(NBLK - 1));
    }
    __syncthreads();
    if (!amLast) return;

    // ---- finalize (parallel) ----
    __shared__ double pr[7];
    if (tid < 7) {
        double s = 0;
        #pragma unroll
        for (int k = 0; k < K1B; k++) s += g_part[tid][k];
        pr[tid] = s;
    }
    __syncthreads();
    if (tid == 0) {
        double bce_s = pr[0], nf = pr[1], W = pr[2];
        double Sp = pr[3], Sp2 = pr[4], St = pr[5], St2 = pr[6];

        double Paa = 2.0 * (W * Sp2 - Sp * Sp);
        double Pbb = 2.0 * (W * St2 - St * St);
        double sa = g_S[0], sb = g_S[1], qab = g_S[2], qaa = g_S[3], qbb = g_S[4];

        double inv2 = 1.0 / (nf * nf);
        double at = sa * inv2;
        double bt = sb * inv2;
        double cQ = (2.0 * W - 4.0 * nf) * inv2;
        double cT = 4.0 * nf * nf - 4.0 * W * nf + W * W;

        double SAB = g_Pab + cQ * qab + at * bt * cT;
        double SAA = Paa   + cQ * qaa + at * at * cT;
        double SBB = Pbb   + cQ * qbb + bt * bt * cT;

        double bce   = bce_s / (double)n;
        double dcorr = (SAB * SAB) / (SAA * SBB);
        double ld    = DISCO_LAMBDA * dcorr;
        out[0] = (float)(bce + ld);
        out[1] = (float)bce;
        out[2] = (float)ld;
    }
    // re-zero scratch for next graph replay
    for (int b = tid; b < NB; b += TB4) {
        g_Wbp[b] = 0.0; g_Xbp[b] = 0.0;
        g_Wbt[b] = 0.0; g_Xbt[b] = 0.0;
        g_cntp[b] = 0;  g_cntt[b] = 0;
    }
    if (tid < 5) g_S[tid] = 0.0;
    if (tid == 0) { g_Pab = 0.0; g_ticket = 0u; }
}

// ---------------------------------------------------------------------------
extern "C" void kernel_launch(void* const* d_in, const int* in_sizes, int n_in,
                              void* d_out, int out_size) {
    const float* p   = (const float*)d_in[0];  // inferences
    const int*   lab = (const int*)  d_in[1];  // labels
    const float* t   = (const float*)d_in[2];  // disco_target
    const float* w   = (const float*)d_in[3];  // weights
    float* out = (float*)d_out;
    int n = in_sizes[0];

    k_prep<<<K1B, K1T>>>(p, lab, t, w, n);
    k_uv<<<n / 256, 256>>>(p, t, n);
    dim3 grid(n / (TB4 * ROWS), GY);   // 16 x 64 = 1024 blocks of 128
    k_pab<<<grid, TB4>>>(p, t, out, n);
}